// round 6
// baseline (speedup 1.0000x reference)
#include <cuda_runtime.h>
#include <cuda_bf16.h>
#include <cstdint>

#define NROWS 50000
#define KNB   32
#define CDIM  128
#define TOPK  16
#define RB    8        // rows per block
#define NCHUNK 16      // M/Ws d-chunks
#define DCH    8       // d per chunk

// ---------------- scratch (device globals; no allocation) ----------------
__device__ __align__(16) float g_M [CDIM * CDIM];     // Wq^T @ Wk
__device__ __align__(16) float g_Ws[CDIM * CDIM];     // triu(W) + triu(W)^T
__device__ __align__(16) float g_scores[(size_t)NROWS * KNB];
__device__ int g_colmask[KNB];
__device__ int g_needfix;
__device__ int g_mask_narrow;   // 1 -> mask elements are 1 byte; 0 -> 4 bytes

// ---------------- cp.async helpers ----------------
__device__ __forceinline__ void cp_async16(void* smem_dst, const void* gptr) {
    uint32_t s = (uint32_t)__cvta_generic_to_shared(smem_dst);
    asm volatile("cp.async.cg.shared.global [%0], [%1], 16;\n" :: "r"(s), "l"(gptr));
}
__device__ __forceinline__ void cp_async_commit() {
    asm volatile("cp.async.commit_group;\n" ::: "memory");
}
template <int N> __device__ __forceinline__ void cp_async_wait() {
    asm volatile("cp.async.wait_group %0;\n" :: "n"(N) : "memory");
}

// ---------------- K0: prep M, Ws, reset flags ----------------
__global__ void prep_kernel(const float* __restrict__ Wq,
                            const float* __restrict__ Wk,
                            const float* __restrict__ W) {
    int c = blockIdx.x;    // 0..127
    int e = threadIdx.x;   // 0..127
    float acc = 0.f;
#pragma unroll 8
    for (int d = 0; d < CDIM; d++)
        acc += Wq[d * CDIM + c] * Wk[d * CDIM + e];
    g_M[c * CDIM + e] = acc;

    float w = (c <= e) ? W[c * CDIM + e] : W[e * CDIM + c];
    g_Ws[c * CDIM + e] = (c == e) ? 2.f * w : w;

    if (c == 0 && e < KNB) g_colmask[e] = 0;
    if (c == 0 && e == KNB) g_needfix = 0;
    if (c == 0 && e == KNB + 1) g_mask_narrow = 0;
}

// ---------------- K0b: sniff knn_mask element width ----------------
__global__ void sniff_kernel(const unsigned int* __restrict__ w) {
    const int nwords = NROWS * KNB / 4;
    int bad = 0;
    for (int i = blockIdx.x * blockDim.x + threadIdx.x; i < nwords;
         i += gridDim.x * blockDim.x) {
        unsigned int v = w[i];
        if (v != 0u && v != 1u && v != 0x3F800000u) bad = 1;
    }
    if (bad) g_mask_narrow = 1;
}

// ---------------- K1: fused projection + streaming kernel ----------------
// One block: 8 rows. Phase A: qM/fW projections with M,Ws streamed from L2 in
// double-buffered 8KB chunks (cost amortized over 8 rows). Phase B: per-row
// scores/topk/softmax/outputs with double-buffered cp.async kf tiles.
//
// dynamic smem layout (floats):
//   kfS    [2][32][128]   @ 0      (32768 B)
//   mwS    [2][M 8x128 | Ws 8x128] @ 8192   (16384 B)
//   featS  [8][128]       @ 12288  (4096 B)
//   qMS    [8][128]       @ 13312
//   fWS    [8][128]       @ 14336
//   xyzS   [8][96]        @ 15360
//   madjS  [8][32]        @ 16128
//   scS[32] mlS[32] attnS[32] redS[4] @ 16384..16484
#define SM_TOTAL_BYTES (16512 * 4)

__global__ void __launch_bounds__(256, 3) fused_kernel(
    const float* __restrict__ feat, const float* __restrict__ knn_xyz,
    const float* __restrict__ knn_feat, const void* __restrict__ knn_mask,
    float* __restrict__ out_xyz, float* __restrict__ out_att, float* __restrict__ out_ml)
{
    extern __shared__ float sm[];
    float* kfS   = sm;
    float* mwS   = sm + 8192;
    float* featS = sm + 12288;
    float* qMS   = sm + 13312;
    float* fWS   = sm + 14336;
    float* xyzS  = sm + 15360;
    float* madjS = sm + 16128;
    float* scS   = sm + 16384;
    float* mlS   = sm + 16416;
    float* attnS = sm + 16448;
    float* redS  = sm + 16480;

    int tid  = threadIdx.x;
    int lane = tid & 31;
    int warp = tid >> 5;
    int n0   = blockIdx.x * RB;

    // group 0: featS + xyzS + MW chunk 0
    cp_async16((float4*)featS + tid,
               (const float4*)(feat + (size_t)n0 * CDIM) + tid);          // 8x128 f
    if (tid < 192)
        cp_async16((float4*)xyzS + tid,
                   (const float4*)(knn_xyz + (size_t)n0 * 96) + tid);     // 8x96 f
    cp_async16((float4*)mwS + tid,          (const float4*)g_M  + tid);
    cp_async16((float4*)(mwS + 1024) + tid, (const float4*)g_Ws + tid);
    cp_async_commit();

    // mask adjust (independent small loads)
    {
        int r = tid >> 5, j = tid & 31;
        bool mv;
        if (g_mask_narrow)
            mv = ((const unsigned char*)knn_mask)[(size_t)(n0 + r) * KNB + j] != 0;
        else
            mv = ((const unsigned int*)knn_mask)[(size_t)(n0 + r) * KNB + j] != 0u;
        madjS[tid] = mv ? 0.f : -1e12f;
    }

    // ---- Phase A: qM/fW projection ----
    // lane -> (row ra = lane>>2, col quad c0 = warp*16 + (lane&3)*4)
    int c0 = warp * 16 + (lane & 3) * 4;
    int ra = lane >> 2;
    float q0 = 0, q1 = 0, q2 = 0, q3 = 0, w0 = 0, w1 = 0, w2 = 0, w3 = 0;

    for (int c = 0; c < NCHUNK; c++) {
        if (c + 1 < NCHUNK) {
            float* dst = mwS + ((c + 1) & 1) * 2048;
            cp_async16((float4*)dst + tid,
                       (const float4*)g_M  + (c + 1) * 256 + tid);
            cp_async16((float4*)(dst + 1024) + tid,
                       (const float4*)g_Ws + (c + 1) * 256 + tid);
            cp_async_commit();
        } else {
            // prefetch kf for row 0 (completes in commit order after chunk 15)
            const float4* src = (const float4*)(knn_feat + (size_t)n0 * (KNB * CDIM));
            float4* dst = (float4*)kfS;
#pragma unroll
            for (int i = 0; i < 4; i++)
                cp_async16(dst + i * 256 + tid, src + i * 256 + tid);
            cp_async_commit();
        }
        cp_async_wait<1>();     // chunk c landed
        __syncthreads();

        const float* Ms  = mwS + (c & 1) * 2048;
        const float* Wss = Ms + 1024;
        const float* fp  = featS + ra * CDIM + c * DCH;
#pragma unroll
        for (int d = 0; d < DCH; d++) {
            float  f  = fp[d];
            float4 m4 = *(const float4*)(Ms  + d * CDIM + c0);
            float4 s4 = *(const float4*)(Wss + d * CDIM + c0);
            q0 += f * m4.x; q1 += f * m4.y; q2 += f * m4.z; q3 += f * m4.w;
            w0 += f * s4.x; w1 += f * s4.y; w2 += f * s4.z; w3 += f * s4.w;
        }
        __syncthreads();
    }
    *(float4*)(qMS + ra * CDIM + c0) = make_float4(q0, q1, q2, q3);
    *(float4*)(fWS + ra * CDIM + c0) = make_float4(w0, w1, w2, w3);
    __syncthreads();

    // ---- Phase B: per-row pipeline, double-buffered kf ----
    for (int r = 0; r < RB; r++) {
        if (r + 1 < RB) {
            const float4* src = (const float4*)(knn_feat + (size_t)(n0 + r + 1) * (KNB * CDIM));
            float4* dst = (float4*)(kfS + ((r + 1) & 1) * 4096);
#pragma unroll
            for (int i = 0; i < 4; i++)
                cp_async16(dst + i * 256 + tid, src + i * 256 + tid);
            cp_async_commit();
            cp_async_wait<1>();   // kf r ready (kf r+1 may pend)
        } else {
            cp_async_wait<0>();
        }
        __syncthreads();

        const float* kf = kfS + (r & 1) * 4096;
        int n = n0 + r;

        // dots: warp w handles neighbors 4w..4w+3
        float4 qv = *(const float4*)(qMS + r * CDIM + lane * 4);
        float4 fv = *(const float4*)(fWS + r * CDIM + lane * 4);
        int j0 = warp * 4;
        float s[4], ml[4];
#pragma unroll
        for (int jj = 0; jj < 4; jj++) {
            float4 k4 = *(const float4*)(kf + (j0 + jj) * CDIM + lane * 4);
            s [jj] = k4.x * qv.x + k4.y * qv.y + k4.z * qv.z + k4.w * qv.w;
            ml[jj] = k4.x * fv.x + k4.y * fv.y + k4.z * fv.z + k4.w * fv.w;
        }
#pragma unroll
        for (int o = 16; o; o >>= 1) {
#pragma unroll
            for (int jj = 0; jj < 4; jj++) {
                s [jj] += __shfl_xor_sync(0xffffffffu, s [jj], o);
                ml[jj] += __shfl_xor_sync(0xffffffffu, ml[jj], o);
            }
        }
#pragma unroll
        for (int jj = 0; jj < 4; jj++) {
            if (lane == jj) {
                scS[j0 + jj] = s[jj] + madjS[r * KNB + j0 + jj];
                mlS[j0 + jj] = ml[jj];
            }
        }
        __syncthreads();

        // topk rank + colmask + optimistic softmax (warp 0)
        if (tid < KNB) {
            float sj = scS[tid];
            int rank = 0;
#pragma unroll
            for (int i = 0; i < KNB; i++) {
                float si = scS[i];
                rank += (si > sj) || (si == sj && i < tid);  // lax.top_k stable tie rule
            }
            if (rank < TOPK) {
                if (__ldcg(&g_colmask[tid]) == 0) atomicOr(&g_colmask[tid], 1);
            }
            g_scores[(size_t)n * KNB + tid] = sj;
            out_ml[(size_t)n * KNB + tid]   = mlS[tid];

            float m = sj;
#pragma unroll
            for (int o = 16; o; o >>= 1) m = fmaxf(m, __shfl_xor_sync(0xffffffffu, m, o));
            float e = __expf(sj - m);
            float ssum = e;
#pragma unroll
            for (int o = 16; o; o >>= 1) ssum += __shfl_xor_sync(0xffffffffu, ssum, o);
            attnS[tid] = e / ssum;
        }
        __syncthreads();

        // weighted sums + outputs (optimistic: all columns covered)
        if (tid < CDIM) {
            float a0 = 0.f, a1 = 0.f, a2 = 0.f, a3 = 0.f;
#pragma unroll
            for (int j = 0; j < KNB; j += 4) {
                a0 += attnS[j    ] * kf[(j    ) * CDIM + tid];
                a1 += attnS[j + 1] * kf[(j + 1) * CDIM + tid];
                a2 += attnS[j + 2] * kf[(j + 2) * CDIM + tid];
                a3 += attnS[j + 3] * kf[(j + 3) * CDIM + tid];
            }
            float acc = (a0 + a1) + (a2 + a3);

            size_t ob = (size_t)n * 257;
            out_att[ob + tid]       = featS[r * CDIM + tid];
            out_att[ob + 128 + tid] = acc;

            float p = fWS[r * CDIM + tid] * acc;
#pragma unroll
            for (int o = 16; o; o >>= 1) p += __shfl_xor_sync(0xffffffffu, p, o);
            if (lane == 0) redS[warp] = p;
        }
        __syncthreads();
        if (tid == 0)
            out_att[(size_t)n * 257 + 256] = redS[0] + redS[1] + redS[2] + redS[3];
        if (tid < 3) {
            float x = 0.f;
#pragma unroll
            for (int j = 0; j < KNB; j++) x += attnS[j] * xyzS[r * 96 + j * 3 + tid];
            out_xyz[(size_t)n * 3 + tid] = x;
        }
        __syncthreads();
    }
}

// ---------------- K2: check whether any column never made top-k ----------------
__global__ void check_kernel() {
    int nf = 0;
    for (int j = 0; j < KNB; j++) nf |= (g_colmask[j] == 0);
    g_needfix = nf;
}

// ---------------- K3: fixup (rare path; recomputes fW from g_Ws) ----------------
__global__ void __launch_bounds__(128) fixup_kernel(
    const float* __restrict__ feat, const float* __restrict__ knn_feat,
    const float* __restrict__ knn_xyz,
    float* __restrict__ out_xyz, float* __restrict__ out_att)
{
    if (g_needfix == 0) return;   // common case

    __shared__ float attnS[KNB];
    __shared__ float redS[4];
    __shared__ int   colS[KNB];
    int tid = threadIdx.x, lane = tid & 31, warp = tid >> 5;
    if (tid < KNB) colS[tid] = g_colmask[tid];
    __syncthreads();

    for (int n = blockIdx.x; n < NROWS; n += gridDim.x) {
        if (tid < KNB) {
            float s  = g_scores[(size_t)n * KNB + tid];
            int inc  = colS[tid];
            float se = inc ? s : -3.0e38f;
            float m = se;
#pragma unroll
            for (int o = 16; o; o >>= 1) m = fmaxf(m, __shfl_xor_sync(0xffffffffu, m, o));
            float e = inc ? __expf(se - m) : 0.f;
            float ssum = e;
#pragma unroll
            for (int o = 16; o; o >>= 1) ssum += __shfl_xor_sync(0xffffffffu, ssum, o);
            attnS[tid] = e / ssum;
        }
        __syncthreads();

        float acc = 0.f;
#pragma unroll
        for (int j = 0; j < KNB; j++)
            acc += attnS[j] * knn_feat[(size_t)n * (KNB * CDIM) + j * CDIM + tid];

        size_t ob = (size_t)n * 257;
        out_att[ob + 128 + tid] = acc;

        // recompute fW row (g_fW scratch no longer exists)
        float fwv = 0.f;
#pragma unroll 8
        for (int d = 0; d < CDIM; d++)
            fwv += __ldg(&feat[(size_t)n * CDIM + d]) * g_Ws[d * CDIM + tid];

        float p = fwv * acc;
#pragma unroll
        for (int o = 16; o; o >>= 1) p += __shfl_xor_sync(0xffffffffu, p, o);
        if (lane == 0) redS[warp] = p;
        __syncthreads();
        if (tid == 0) out_att[ob + 256] = redS[0] + redS[1] + redS[2] + redS[3];

        if (tid < 3) {
            float x = 0.f;
#pragma unroll
            for (int j = 0; j < KNB; j++)
                x += attnS[j] * knn_xyz[(size_t)n * (KNB * 3) + j * 3 + tid];
            out_xyz[(size_t)n * 3 + tid] = x;
        }
        __syncthreads();
    }
}

// ---------------- launch ----------------
extern "C" void kernel_launch(void* const* d_in, const int* in_sizes, int n_in,
                              void* d_out, int out_size) {
    const float* feat     = (const float*)d_in[0];          // [N,128]
    const float* knn_xyz  = (const float*)d_in[1];          // [N,32,3]
    const float* knn_feat = (const float*)d_in[2];          // [N,32,128]
    const void*  knn_mask = d_in[3];                        // [N,32] bool (width sniffed)
    const float* Wq       = (const float*)d_in[4];          // [128,128]
    const float* Wk       = (const float*)d_in[5];          // [128,128]
    const float* W        = (const float*)d_in[6];          // [128,128]

    float* out     = (float*)d_out;
    float* out_xyz = out;                                   // [N,3]
    float* out_att = out + (size_t)NROWS * 3;               // [N,257]
    float* out_ml  = out + (size_t)NROWS * 3 + (size_t)NROWS * 257;  // [N,32]

    prep_kernel<<<CDIM, CDIM>>>(Wq, Wk, W);
    sniff_kernel<<<512, 256>>>((const unsigned int*)knn_mask);

    cudaFuncSetAttribute(fused_kernel, cudaFuncAttributeMaxDynamicSharedMemorySize,
                         SM_TOTAL_BYTES);
    fused_kernel<<<NROWS / RB, 256, SM_TOTAL_BYTES>>>(
        feat, knn_xyz, knn_feat, knn_mask, out_xyz, out_att, out_ml);

    check_kernel<<<1, 1>>>();
    fixup_kernel<<<2048, CDIM>>>(feat, knn_feat, knn_xyz, out_xyz, out_att);
}

// round 7
// speedup vs baseline: 1.3061x; 1.3061x over previous
#include <cuda_runtime.h>
#include <cuda_bf16.h>
#include <cstdint>

#define NROWS 50000
#define KNB   32
#define CDIM  128
#define TOPK  16

// ---------------- scratch (device globals; no allocation) ----------------
__device__ __align__(16) float g_M [CDIM * CDIM];     // Wq^T @ Wk
__device__ __align__(16) float g_Ws[CDIM * CDIM];     // triu(W) + triu(W)^T
__device__ __align__(16) float g_qM[(size_t)NROWS * CDIM];  // feat @ M
__device__ __align__(16) float g_fW[(size_t)NROWS * CDIM];  // feat @ Ws
__device__ __align__(16) float g_scores[(size_t)NROWS * KNB];
__device__ int g_colmask[KNB];
__device__ int g_needfix;
__device__ int g_mask_narrow;   // 1 -> mask elements are 1 byte; 0 -> 4 bytes

// ---------------- cp.async helpers ----------------
__device__ __forceinline__ void cp_async16(void* smem_dst, const void* gptr) {
    uint32_t s = (uint32_t)__cvta_generic_to_shared(smem_dst);
    asm volatile("cp.async.cg.shared.global [%0], [%1], 16;\n" :: "r"(s), "l"(gptr));
}
__device__ __forceinline__ void cp_async_commit() {
    asm volatile("cp.async.commit_group;\n" ::: "memory");
}
template <int N> __device__ __forceinline__ void cp_async_wait() {
    asm volatile("cp.async.wait_group %0;\n" :: "n"(N) : "memory");
}

// ---------------- K0: prep M, Ws, reset flags ----------------
__global__ void prep_kernel(const float* __restrict__ Wq,
                            const float* __restrict__ Wk,
                            const float* __restrict__ W) {
    int c = blockIdx.x;    // 0..127
    int e = threadIdx.x;   // 0..127
    float acc = 0.f;
#pragma unroll 8
    for (int d = 0; d < CDIM; d++)
        acc += Wq[d * CDIM + c] * Wk[d * CDIM + e];
    g_M[c * CDIM + e] = acc;

    float w = (c <= e) ? W[c * CDIM + e] : W[e * CDIM + c];
    g_Ws[c * CDIM + e] = (c == e) ? 2.f * w : w;

    if (c == 0 && e < KNB) g_colmask[e] = 0;
    if (c == 0 && e == KNB) g_needfix = 0;
    if (c == 0 && e == KNB + 1) g_mask_narrow = 0;
}

// ---------------- K0b: sniff knn_mask element width ----------------
__global__ void sniff_kernel(const unsigned int* __restrict__ w) {
    const int nwords = NROWS * KNB / 4;
    int bad = 0;
    for (int i = blockIdx.x * blockDim.x + threadIdx.x; i < nwords;
         i += gridDim.x * blockDim.x) {
        unsigned int v = w[i];
        if (v != 0u && v != 1u && v != 0x3F800000u) bad = 1;
    }
    if (bad) g_mask_narrow = 1;
}

// ---------------- K1: SGEMM v3  [N,128]@[128,128] x2 ----------------
// A tile (64 rows) in smem; B (g_M + g_Ws = 128KB) read via LDG -> L1-resident
// (identical addresses across all blocks; 32KB smem leaves 164KB+ L1D).
// Per-thread microtile 4 rows x 8 cols x 2 matrices -> FMA-bound (4:1 vs L1).
__global__ void __launch_bounds__(256, 2) gemm_kernel(const float* __restrict__ A) {
    __shared__ __align__(16) float As[64 * 128];   // 32 KB

    int tid  = threadIdx.x;
    int row0 = blockIdx.x * 64;

    for (int i = tid; i < 64 * 32; i += 256) {     // float4 units
        int r = i >> 5;
        float4 v = make_float4(0.f, 0.f, 0.f, 0.f);
        if (row0 + r < NROWS)
            v = reinterpret_cast<const float4*>(A)[(size_t)(row0 + r) * 32 + (i & 31)];
        reinterpret_cast<float4*>(As)[i] = v;
    }
    __syncthreads();

    int cq = tid & 15;   // cols cq*8 .. cq*8+7
    int rg = tid >> 4;   // rows rg*4 .. rg*4+3
    float accM[4][8], accW[4][8];
#pragma unroll
    for (int i = 0; i < 4; i++)
#pragma unroll
        for (int j = 0; j < 8; j++) { accM[i][j] = 0.f; accW[i][j] = 0.f; }

    const float* Arow = As + rg * 4 * 128;
#pragma unroll 4
    for (int k = 0; k < 128; k++) {
        float a[4];
#pragma unroll
        for (int i = 0; i < 4; i++) a[i] = Arow[i * 128 + k];
        float4 m0 = __ldg((const float4*)(g_M  + k * 128 + cq * 8));
        float4 m1 = __ldg((const float4*)(g_M  + k * 128 + cq * 8 + 4));
        float4 w0 = __ldg((const float4*)(g_Ws + k * 128 + cq * 8));
        float4 w1 = __ldg((const float4*)(g_Ws + k * 128 + cq * 8 + 4));
        float bm[8] = {m0.x, m0.y, m0.z, m0.w, m1.x, m1.y, m1.z, m1.w};
        float bw[8] = {w0.x, w0.y, w0.z, w0.w, w1.x, w1.y, w1.z, w1.w};
#pragma unroll
        for (int i = 0; i < 4; i++)
#pragma unroll
            for (int j = 0; j < 8; j++) {
                accM[i][j] += a[i] * bm[j];
                accW[i][j] += a[i] * bw[j];
            }
    }

#pragma unroll
    for (int i = 0; i < 4; i++) {
        int r = row0 + rg * 4 + i;
        if (r < NROWS) {
            float4* pq = reinterpret_cast<float4*>(g_qM + (size_t)r * 128 + cq * 8);
            float4* pf = reinterpret_cast<float4*>(g_fW + (size_t)r * 128 + cq * 8);
            pq[0] = make_float4(accM[i][0], accM[i][1], accM[i][2], accM[i][3]);
            pq[1] = make_float4(accM[i][4], accM[i][5], accM[i][6], accM[i][7]);
            pf[0] = make_float4(accW[i][0], accW[i][1], accW[i][2], accW[i][3]);
            pf[1] = make_float4(accW[i][4], accW[i][5], accW[i][6], accW[i][7]);
        }
    }
}

// ---------------- K2: streaming kernel, 2 rows per block (parallel halves) ----
// Each 128-thread half runs the proven R5 per-row pipeline; both kf tiles'
// cp.asyncs issue at block start -> doubled DRAM duty per block.
__global__ void __launch_bounds__(256, 5) main_kernel(
    const float* __restrict__ feat, const float* __restrict__ knn_xyz,
    const float* __restrict__ knn_feat, const void* __restrict__ knn_mask,
    float* __restrict__ out_xyz, float* __restrict__ out_att, float* __restrict__ out_ml)
{
    __shared__ __align__(16) float kfS[2][KNB * CDIM];   // 2 x 16 KB
    __shared__ __align__(16) float qMS[2][CDIM];
    __shared__ __align__(16) float fWS[2][CDIM];
    __shared__ float xyzS[2][KNB * 3];
    __shared__ float madjS[2][KNB];
    __shared__ float scS[2][KNB], mlS[2][KNB], attnS[2][KNB];
    __shared__ float redS[2][4];

    int tid  = threadIdx.x;
    int h    = tid >> 7;     // half
    int t    = tid & 127;
    int lane = t & 31;
    int w4   = t >> 5;       // warp within half (0..3)
    int n    = blockIdx.x * 2 + h;

    // both halves issue their kf tile immediately (global -> smem, L1-bypass)
    {
        float4*       dst = reinterpret_cast<float4*>(kfS[h]);
        const float4* src = reinterpret_cast<const float4*>(knn_feat + (size_t)n * (KNB * CDIM));
#pragma unroll
        for (int i = 0; i < 8; i++)
            cp_async16(dst + i * 128 + t, src + i * 128 + t);
        cp_async_commit();
    }

    // overlapped small loads
    float fc = __ldg(&feat[(size_t)n * CDIM + t]);
    qMS[h][t] = g_qM[(size_t)n * CDIM + t];
    fWS[h][t] = g_fW[(size_t)n * CDIM + t];
    if (t < KNB * 3) xyzS[h][t] = knn_xyz[(size_t)n * (KNB * 3) + t];
    if (t < KNB) {
        bool mv;
        if (g_mask_narrow)
            mv = ((const unsigned char*)knn_mask)[(size_t)n * KNB + t] != 0;
        else
            mv = ((const unsigned int*)knn_mask)[(size_t)n * KNB + t] != 0u;
        madjS[h][t] = mv ? 0.f : -1e12f;
    }
    cp_async_wait<0>();
    __syncthreads();

    float4 qv = reinterpret_cast<const float4*>(qMS[h])[lane];
    float4 fv = reinterpret_cast<const float4*>(fWS[h])[lane];

    // dots: warp w4 handles neighbors 8*w4 .. 8*w4+7 of row n
    int j0 = w4 * 8;
    float s[8], ml[8];
#pragma unroll
    for (int jj = 0; jj < 8; jj++) {
        float4 k4 = reinterpret_cast<const float4*>(kfS[h] + (j0 + jj) * CDIM)[lane];
        s [jj] = k4.x * qv.x + k4.y * qv.y + k4.z * qv.z + k4.w * qv.w;
        ml[jj] = k4.x * fv.x + k4.y * fv.y + k4.z * fv.z + k4.w * fv.w;
    }
#pragma unroll
    for (int o = 16; o; o >>= 1) {
#pragma unroll
        for (int jj = 0; jj < 8; jj++) {
            s [jj] += __shfl_xor_sync(0xffffffffu, s [jj], o);
            ml[jj] += __shfl_xor_sync(0xffffffffu, ml[jj], o);
        }
    }
#pragma unroll
    for (int jj = 0; jj < 8; jj++) {
        if (lane == jj) {
            scS[h][j0 + jj] = s[jj] + madjS[h][j0 + jj];
            mlS[h][j0 + jj] = ml[jj];
        }
    }
    __syncthreads();

    // topk rank + colmask + optimistic softmax (first warp of each half)
    if (t < KNB) {
        float sj = scS[h][t];
        int rank = 0;
#pragma unroll
        for (int i = 0; i < KNB; i++) {
            float si = scS[h][i];
            rank += (si > sj) || (si == sj && i < t);   // lax.top_k stable tie rule
        }
        if (rank < TOPK) {
            if (__ldcg(&g_colmask[t]) == 0) atomicOr(&g_colmask[t], 1);
        }
        g_scores[(size_t)n * KNB + t] = sj;
        out_ml[(size_t)n * KNB + t]   = mlS[h][t];

        float m = sj;
#pragma unroll
        for (int o = 16; o; o >>= 1) m = fmaxf(m, __shfl_xor_sync(0xffffffffu, m, o));
        float e = __expf(sj - m);
        float ssum = e;
#pragma unroll
        for (int o = 16; o; o >>= 1) ssum += __shfl_xor_sync(0xffffffffu, ssum, o);
        attnS[h][t] = e / ssum;
    }
    __syncthreads();

    // weighted sums + outputs (optimistic: all columns covered)
    float a0 = 0.f, a1 = 0.f, a2 = 0.f, a3 = 0.f;
#pragma unroll
    for (int j = 0; j < KNB; j += 4) {
        a0 += attnS[h][j    ] * kfS[h][(j    ) * CDIM + t];
        a1 += attnS[h][j + 1] * kfS[h][(j + 1) * CDIM + t];
        a2 += attnS[h][j + 2] * kfS[h][(j + 2) * CDIM + t];
        a3 += attnS[h][j + 3] * kfS[h][(j + 3) * CDIM + t];
    }
    float acc = (a0 + a1) + (a2 + a3);

    size_t ob = (size_t)n * 257;
    out_att[ob + t]       = fc;     // attentive_feats[:, 0:128] = feat
    out_att[ob + 128 + t] = acc;    // attentive_feats[:, 128:256] = corres_feat

    float p = fWS[h][t] * acc;
#pragma unroll
    for (int o = 16; o; o >>= 1) p += __shfl_xor_sync(0xffffffffu, p, o);
    if (lane == 0) redS[h][w4] = p;
    __syncthreads();
    if (t == 0)
        out_att[ob + 256] = redS[h][0] + redS[h][1] + redS[h][2] + redS[h][3];  // logit

    if (t < 3) {
        float x = 0.f;
#pragma unroll
        for (int j = 0; j < KNB; j++) x += attnS[h][j] * xyzS[h][j * 3 + t];
        out_xyz[(size_t)n * 3 + t] = x;
    }
}

// ---------------- K3: check whether any column never made top-k ----------------
__global__ void check_kernel() {
    int t = threadIdx.x;
    int miss = (t < KNB && g_colmask[t] == 0) ? 1 : 0;
#pragma unroll
    for (int o = 16; o; o >>= 1) miss |= __shfl_xor_sync(0xffffffffu, miss, o);
    if (t == 0) g_needfix = miss;
}

// ---------------- K4: fixup (early-exits when colmask is all-covered) ----------------
__global__ void __launch_bounds__(128) fixup_kernel(
    const float* __restrict__ knn_feat, const float* __restrict__ knn_xyz,
    float* __restrict__ out_xyz, float* __restrict__ out_att)
{
    if (g_needfix == 0) return;   // common case

    __shared__ float attnS[KNB];
    __shared__ float redS[4];
    __shared__ int   colS[KNB];
    int tid = threadIdx.x, lane = tid & 31, warp = tid >> 5;
    if (tid < KNB) colS[tid] = g_colmask[tid];
    __syncthreads();

    for (int n = blockIdx.x; n < NROWS; n += gridDim.x) {
        if (tid < KNB) {
            float s  = g_scores[(size_t)n * KNB + tid];
            int inc  = colS[tid];
            float se = inc ? s : -3.0e38f;
            float m = se;
#pragma unroll
            for (int o = 16; o; o >>= 1) m = fmaxf(m, __shfl_xor_sync(0xffffffffu, m, o));
            float e = inc ? __expf(se - m) : 0.f;
            float ssum = e;
#pragma unroll
            for (int o = 16; o; o >>= 1) ssum += __shfl_xor_sync(0xffffffffu, ssum, o);
            attnS[tid] = e / ssum;
        }
        __syncthreads();

        float acc = 0.f;
#pragma unroll
        for (int j = 0; j < KNB; j++)
            acc += attnS[j] * knn_feat[(size_t)n * (KNB * CDIM) + j * CDIM + tid];

        size_t ob = (size_t)n * 257;
        out_att[ob + 128 + tid] = acc;

        float p = g_fW[(size_t)n * CDIM + tid] * acc;
#pragma unroll
        for (int o = 16; o; o >>= 1) p += __shfl_xor_sync(0xffffffffu, p, o);
        if (lane == 0) redS[warp] = p;
        __syncthreads();
        if (tid == 0) out_att[ob + 256] = redS[0] + redS[1] + redS[2] + redS[3];

        if (tid < 3) {
            float x = 0.f;
#pragma unroll
            for (int j = 0; j < KNB; j++)
                x += attnS[j] * knn_xyz[(size_t)n * (KNB * 3) + j * 3 + tid];
            out_xyz[(size_t)n * 3 + tid] = x;
        }
        __syncthreads();
    }
}

// ---------------- launch ----------------
extern "C" void kernel_launch(void* const* d_in, const int* in_sizes, int n_in,
                              void* d_out, int out_size) {
    const float* feat     = (const float*)d_in[0];          // [N,128]
    const float* knn_xyz  = (const float*)d_in[1];          // [N,32,3]
    const float* knn_feat = (const float*)d_in[2];          // [N,32,128]
    const void*  knn_mask = d_in[3];                        // [N,32] bool (width sniffed)
    const float* Wq       = (const float*)d_in[4];          // [128,128]
    const float* Wk       = (const float*)d_in[5];          // [128,128]
    const float* W        = (const float*)d_in[6];          // [128,128]

    float* out     = (float*)d_out;
    float* out_xyz = out;                                   // [N,3]
    float* out_att = out + (size_t)NROWS * 3;               // [N,257]
    float* out_ml  = out + (size_t)NROWS * 3 + (size_t)NROWS * 257;  // [N,32]

    prep_kernel<<<CDIM, CDIM>>>(Wq, Wk, W);
    sniff_kernel<<<512, 256>>>((const unsigned int*)knn_mask);

    gemm_kernel<<<(NROWS + 63) / 64, 256>>>(feat);

    main_kernel<<<NROWS / 2, 256>>>(feat, knn_xyz, knn_feat, knn_mask,
                                    out_xyz, out_att, out_ml);

    check_kernel<<<1, 32>>>();
    fixup_kernel<<<2048, CDIM>>>(knn_feat, knn_xyz, out_xyz, out_att);
}